// round 1
// baseline (speedup 1.0000x reference)
#include <cuda_runtime.h>
#include <math.h>

#define HIDDEN   128
#define FEATURE  264
#define N_NODES  400000
#define HEAD_OFF 39     // 4 + 5 + 30 outputs before teleport logits

// Scratch for the precomputed per-hidden-unit constant
// c[j] = b_tp1[j] + h_glob @ W_tp1[0:128, j] + state @ W_tp1[256:264, j]
__device__ float g_c[HIDDEN];

// ---------------------------------------------------------------------------
// Kernel A: the three tiny heads on feats = [node_hidden[0] | h_glob | state],
// plus precompute g_c for the teleport GEMM. Single block, 128 threads.
// ---------------------------------------------------------------------------
__device__ __forceinline__ void head_ffn(
    const float* __restrict__ feats_s, float* __restrict__ hid_s,
    const float* __restrict__ W1, const float* __restrict__ b1,
    const float* __restrict__ W2, const float* __restrict__ b2,
    int outd, float* __restrict__ out, const float* __restrict__ mask, int tid)
{
    float a = b1[tid];
    #pragma unroll 8
    for (int k = 0; k < FEATURE; k++)
        a = fmaf(feats_s[k], W1[k * HIDDEN + tid], a);
    hid_s[tid] = fmaxf(a, 0.0f);
    __syncthreads();
    if (tid < outd) {
        float o = b2[tid];
        #pragma unroll 8
        for (int k = 0; k < HIDDEN; k++)
            o = fmaf(hid_s[k], W2[k * outd + tid], o);
        if (mask) o += logf(mask[tid]);
        out[tid] = o;
    }
    __syncthreads();
}

__global__ void head_kernel(
    const float* __restrict__ node_hidden, const float* __restrict__ h_glob,
    const float* __restrict__ state,       const float* __restrict__ mask,
    const float* __restrict__ W_hl1, const float* __restrict__ b_hl1,
    const float* __restrict__ W_hl2, const float* __restrict__ b_hl2,
    const float* __restrict__ W_in1, const float* __restrict__ b_in1,
    const float* __restrict__ W_in2, const float* __restrict__ b_in2,
    const float* __restrict__ W_ex1, const float* __restrict__ b_ex1,
    const float* __restrict__ W_ex2, const float* __restrict__ b_ex2,
    const float* __restrict__ W_tp1, const float* __restrict__ b_tp1,
    float* __restrict__ out)
{
    __shared__ float feats[FEATURE];
    __shared__ float hid[HIDDEN];
    const int tid = threadIdx.x;  // 128 threads

    feats[tid]       = node_hidden[tid];   // cur = node 0
    feats[128 + tid] = h_glob[tid];
    if (tid < 8) feats[256 + tid] = state[tid];
    __syncthreads();

    head_ffn(feats, hid, W_hl1, b_hl1, W_hl2, b_hl2,  4, out + 0, nullptr, tid);
    head_ffn(feats, hid, W_in1, b_in1, W_in2, b_in2,  5, out + 4, nullptr, tid);
    head_ffn(feats, hid, W_ex1, b_ex1, W_ex2, b_ex2, 30, out + 9, mask,    tid);

    // c[j] for the teleport GEMM (node-independent part of the first layer)
    float c = b_tp1[tid];
    #pragma unroll 8
    for (int k = 0; k < 128; k++)
        c = fmaf(h_glob[k], W_tp1[k * HIDDEN + tid], c);
    #pragma unroll
    for (int k = 0; k < 8; k++)
        c = fmaf(state[k], W_tp1[(256 + k) * HIDDEN + tid], c);
    g_c[tid] = c;
}

// ---------------------------------------------------------------------------
// Kernel B: fused teleport GEMM.
//   H = relu(c + X @ W)  (X: 400000x128, W = W_tp1[128:256,:] 128x128)
//   y = H @ w2 + b2      (fused in epilogue; only y is written)
// Register-tiled SGEMM: BM=128 nodes, BN=128 (all hidden), BK=16,
// 256 threads, 8x8 microtile per thread (split 4+4 for conflict-free LDS.128).
// ---------------------------------------------------------------------------
#define BM  128
#define BK  16
#define LDS_STRIDE 132   // 128 + 4 padding to break STS bank conflicts

__global__ void __launch_bounds__(256, 2) teleport_kernel(
    const float* __restrict__ X, const float* __restrict__ W_tp1,
    const float* __restrict__ W_tp2, const float* __restrict__ b_tp2,
    float* __restrict__ out)
{
    __shared__ float Xs[BK][LDS_STRIDE];
    __shared__ float Ws[BK][LDS_STRIDE];

    const int tid = threadIdx.x;
    const int tx = tid & 15;      // hidden-dim group (16)
    const int ty = tid >> 4;      // node-dim group  (16)
    const int node0 = blockIdx.x * BM;

    const float* __restrict__ Wb = W_tp1 + 128 * HIDDEN;  // rows 128..255

    float acc[8][8];
    #pragma unroll
    for (int i = 0; i < 8; i++)
        #pragma unroll
        for (int j = 0; j < 8; j++) acc[i][j] = 0.0f;

    // Loader indices (fixed across k-tiles)
    const int lm = tid >> 2;          // 0..63 node within half-tile
    const int lk = (tid & 3) * 4;     // k quad within tile
    const int wk = tid >> 5;          // 0..7 W row within half-tile
    const int wj = (tid & 31) * 4;    // col quad

    for (int kt = 0; kt < HIDDEN; kt += BK) {
        // X tile -> Xs[k][m] (transposed)
        float4 v0 = *(const float4*)(X + (size_t)(node0 + lm)      * HIDDEN + kt + lk);
        float4 v1 = *(const float4*)(X + (size_t)(node0 + lm + 64) * HIDDEN + kt + lk);
        Xs[lk + 0][lm] = v0.x; Xs[lk + 1][lm] = v0.y;
        Xs[lk + 2][lm] = v0.z; Xs[lk + 3][lm] = v0.w;
        Xs[lk + 0][lm + 64] = v1.x; Xs[lk + 1][lm + 64] = v1.y;
        Xs[lk + 2][lm + 64] = v1.z; Xs[lk + 3][lm + 64] = v1.w;

        // W tile -> Ws[k][j]
        float4 w0 = *(const float4*)(Wb + (size_t)(kt + wk)     * HIDDEN + wj);
        float4 w1 = *(const float4*)(Wb + (size_t)(kt + wk + 8) * HIDDEN + wj);
        *(float4*)&Ws[wk][wj]     = w0;
        *(float4*)&Ws[wk + 8][wj] = w1;

        __syncthreads();

        #pragma unroll
        for (int kk = 0; kk < BK; kk++) {
            float a[8], b[8];
            *(float4*)(a)     = *(const float4*)&Xs[kk][ty * 4];
            *(float4*)(a + 4) = *(const float4*)&Xs[kk][64 + ty * 4];
            *(float4*)(b)     = *(const float4*)&Ws[kk][tx * 4];
            *(float4*)(b + 4) = *(const float4*)&Ws[kk][64 + tx * 4];
            #pragma unroll
            for (int i = 0; i < 8; i++)
                #pragma unroll
                for (int j = 0; j < 8; j++)
                    acc[i][j] = fmaf(a[i], b[j], acc[i][j]);
        }
        __syncthreads();
    }

    // Epilogue: relu(acc + c[j]) dot w2[j], reduce across the 16 tx lanes.
    float cj[8], w2[8];
    #pragma unroll
    for (int r = 0; r < 4; r++) {
        cj[r]     = g_c[tx * 4 + r];
        cj[4 + r] = g_c[64 + tx * 4 + r];
        w2[r]     = W_tp2[tx * 4 + r];
        w2[4 + r] = W_tp2[64 + tx * 4 + r];
    }
    const float bias2 = b_tp2[0];

    #pragma unroll
    for (int i = 0; i < 8; i++) {
        float s = 0.0f;
        #pragma unroll
        for (int j = 0; j < 8; j++)
            s = fmaf(fmaxf(acc[i][j] + cj[j], 0.0f), w2[j], s);
        // butterfly reduce within the 16-lane tx group
        s += __shfl_xor_sync(0xffffffffu, s, 1);
        s += __shfl_xor_sync(0xffffffffu, s, 2);
        s += __shfl_xor_sync(0xffffffffu, s, 4);
        s += __shfl_xor_sync(0xffffffffu, s, 8);
        if (tx == 0) {
            int m = (i < 4) ? (ty * 4 + i) : (64 + ty * 4 + (i - 4));
            out[HEAD_OFF + node0 + m] = s + bias2;
        }
    }
}

// ---------------------------------------------------------------------------
extern "C" void kernel_launch(void* const* d_in, const int* in_sizes, int n_in,
                              void* d_out, int out_size)
{
    const float* node_hidden = (const float*)d_in[0];
    const float* h_glob      = (const float*)d_in[1];
    const float* state       = (const float*)d_in[2];
    const float* mask        = (const float*)d_in[3];
    const float* W_hl1 = (const float*)d_in[4];
    const float* b_hl1 = (const float*)d_in[5];
    const float* W_hl2 = (const float*)d_in[6];
    const float* b_hl2 = (const float*)d_in[7];
    const float* W_in1 = (const float*)d_in[8];
    const float* b_in1 = (const float*)d_in[9];
    const float* W_in2 = (const float*)d_in[10];
    const float* b_in2 = (const float*)d_in[11];
    const float* W_ex1 = (const float*)d_in[12];
    const float* b_ex1 = (const float*)d_in[13];
    const float* W_ex2 = (const float*)d_in[14];
    const float* b_ex2 = (const float*)d_in[15];
    const float* W_tp1 = (const float*)d_in[16];
    const float* b_tp1 = (const float*)d_in[17];
    const float* W_tp2 = (const float*)d_in[18];
    const float* b_tp2 = (const float*)d_in[19];
    float* out = (float*)d_out;

    head_kernel<<<1, 128>>>(node_hidden, h_glob, state, mask,
                            W_hl1, b_hl1, W_hl2, b_hl2,
                            W_in1, b_in1, W_in2, b_in2,
                            W_ex1, b_ex1, W_ex2, b_ex2,
                            W_tp1, b_tp1, out);

    teleport_kernel<<<N_NODES / BM, 256>>>(node_hidden, W_tp1, W_tp2, b_tp2, out);
}

// round 5
// speedup vs baseline: 1.8343x; 1.8343x over previous
#include <cuda_runtime.h>
#include <math.h>
#include <stdint.h>

#define HIDDEN   128
#define FEATURE  264
#define N_NODES  400000
#define HEAD_OFF 39     // 4 + 5 + 30 outputs before teleport logits

#define BM        128   // nodes per block
#define CHUNK      32   // K per staging chunk
#define XS_STRIDE  36   // 36 % 32 == 4 -> conflict-free A-fragment LDS
#define NCHUNKS     4   // 128 / 32

// c[j] = b_tp1[j] + h_glob @ W_tp1[0:128, j] + state @ W_tp1[256:264, j]
__device__ float  g_c[HIDDEN];
// Prepacked tf32 B fragments of W_tp1[128:256,:]: [kt(16)][nt(16)][lane(32)] -> (b0,b1)
__device__ float2 g_Wfrag[16 * 16 * 32];

__device__ __forceinline__ uint32_t f2tf(float x) {
    uint32_t r;
    asm("cvt.rna.tf32.f32 %0, %1;" : "=r"(r) : "f"(x));
    return r;
}

// ---------------------------------------------------------------------------
// Kernel A: tiny heads + precompute g_c + prepack W fragments.
// ---------------------------------------------------------------------------
__device__ __forceinline__ void head_ffn(
    const float* __restrict__ feats_s, float* __restrict__ hid_s,
    const float* __restrict__ W1, const float* __restrict__ b1,
    const float* __restrict__ W2, const float* __restrict__ b2,
    int outd, float* __restrict__ out, const float* __restrict__ mask, int tid)
{
    float a = b1[tid];
    #pragma unroll 8
    for (int k = 0; k < FEATURE; k++)
        a = fmaf(feats_s[k], W1[k * HIDDEN + tid], a);
    hid_s[tid] = fmaxf(a, 0.0f);
    __syncthreads();
    if (tid < outd) {
        float o = b2[tid];
        #pragma unroll 8
        for (int k = 0; k < HIDDEN; k++)
            o = fmaf(hid_s[k], W2[k * outd + tid], o);
        if (mask) o += logf(mask[tid]);
        out[tid] = o;
    }
    __syncthreads();
}

__global__ void head_kernel(
    const float* __restrict__ node_hidden, const float* __restrict__ h_glob,
    const float* __restrict__ state,       const float* __restrict__ mask,
    const float* __restrict__ W_hl1, const float* __restrict__ b_hl1,
    const float* __restrict__ W_hl2, const float* __restrict__ b_hl2,
    const float* __restrict__ W_in1, const float* __restrict__ b_in1,
    const float* __restrict__ W_in2, const float* __restrict__ b_in2,
    const float* __restrict__ W_ex1, const float* __restrict__ b_ex1,
    const float* __restrict__ W_ex2, const float* __restrict__ b_ex2,
    const float* __restrict__ W_tp1, const float* __restrict__ b_tp1,
    float* __restrict__ out)
{
    __shared__ float feats[FEATURE];
    __shared__ float hid[HIDDEN];
    const int tid = threadIdx.x;  // 128 threads

    feats[tid]       = node_hidden[tid];   // cur = node 0
    feats[128 + tid] = h_glob[tid];
    if (tid < 8) feats[256 + tid] = state[tid];
    __syncthreads();

    head_ffn(feats, hid, W_hl1, b_hl1, W_hl2, b_hl2,  4, out + 0, nullptr, tid);
    head_ffn(feats, hid, W_in1, b_in1, W_in2, b_in2,  5, out + 4, nullptr, tid);
    head_ffn(feats, hid, W_ex1, b_ex1, W_ex2, b_ex2, 30, out + 9, mask,    tid);

    // c[j]: node-independent part of the teleport first layer
    float c = b_tp1[tid];
    #pragma unroll 8
    for (int k = 0; k < 128; k++)
        c = fmaf(h_glob[k], W_tp1[k * HIDDEN + tid], c);
    #pragma unroll
    for (int k = 0; k < 8; k++)
        c = fmaf(state[k], W_tp1[(256 + k) * HIDDEN + tid], c);
    g_c[tid] = c;

    // Prepack tf32 B fragments: B[k][n] = W_tp1[128+k][n]
    // frag (kt, nt, lane): b0 = B[kt*8 + lane%4][nt*8 + lane/4], b1 = same k+4
    for (int idx = tid; idx < 16 * 16 * 32; idx += 128) {
        int t  = idx & 31;
        int nt = (idx >> 5) & 15;
        int kt = idx >> 9;
        int k0 = 128 + kt * 8 + (t & 3);
        int n  = nt * 8 + (t >> 2);
        float b0 = W_tp1[(size_t)k0 * HIDDEN + n];
        float b1 = W_tp1[(size_t)(k0 + 4) * HIDDEN + n];
        g_Wfrag[idx] = make_float2(__uint_as_float(f2tf(b0)),
                                   __uint_as_float(f2tf(b1)));
    }
}

// ---------------------------------------------------------------------------
// Kernel B: tf32 tensor-core teleport GEMM + fused relu/dot epilogue.
//   H = relu(c + X @ W), y = H @ w2 + b2. Only y (400k floats) is written.
// Block: 256 threads (8 warps), tile m128 x n128 x k128.
// Warp tile m32 x n64: 2 m-tiles x 8 n-tiles of mma.m16n8k8.tf32.
// ---------------------------------------------------------------------------
__global__ void __launch_bounds__(256, 2) teleport_kernel(
    const float* __restrict__ X, const float* __restrict__ W_tp2,
    const float* __restrict__ b_tp2, float* __restrict__ out)
{
    extern __shared__ float smem[];
    float2* sW = (float2*)smem;                     // 8192 float2 = 64KB
    float*  Xs = smem + 16384;                      // 2 x 128 x 36 floats

    const int tid  = threadIdx.x;
    const int lane = tid & 31;
    const int warp = tid >> 5;
    const int wm   = warp & 3;       // m group (4)
    const int wn   = warp >> 2;      // n group (2)
    const int g    = lane >> 2;      // groupID (0..7)
    const int tg   = lane & 3;       // thread-in-group (0..3)
    const int node0 = blockIdx.x * BM;

    // Copy prepacked W fragments to smem (16384 floats = 4096 float4)
    {
        const float4* src = (const float4*)g_Wfrag;
        float4* dst = (float4*)sW;
        #pragma unroll
        for (int i = 0; i < 16; i++)
            dst[tid + i * 256] = src[tid + i * 256];
    }

    float acc[2][8][4];
    #pragma unroll
    for (int mt = 0; mt < 2; mt++)
        #pragma unroll
        for (int nt = 0; nt < 8; nt++)
            #pragma unroll
            for (int r = 0; r < 4; r++) acc[mt][nt][r] = 0.0f;

    // Stage chunk 0 into registers (coalesced float4: 4 per thread)
    float4 st[4];
    #pragma unroll
    for (int i = 0; i < 4; i++) {
        int f = tid + i * 256;           // 0..1023
        int row = f >> 3, q = f & 7;
        st[i] = *(const float4*)(X + (size_t)(node0 + row) * HIDDEN + q * 4);
    }

    for (int c = 0; c < NCHUNKS; c++) {
        float* buf = Xs + (c & 1) * (BM * XS_STRIDE);

        // STS current chunk with rna->tf32 conversion
        #pragma unroll
        for (int i = 0; i < 4; i++) {
            int f = tid + i * 256;
            int row = f >> 3, q = f & 7;
            float* p = buf + row * XS_STRIDE + q * 4;
            p[0] = __uint_as_float(f2tf(st[i].x));
            p[1] = __uint_as_float(f2tf(st[i].y));
            p[2] = __uint_as_float(f2tf(st[i].z));
            p[3] = __uint_as_float(f2tf(st[i].w));
        }
        __syncthreads();

        // Prefetch next chunk (overlaps with MMA below)
        if (c < NCHUNKS - 1) {
            #pragma unroll
            for (int i = 0; i < 4; i++) {
                int f = tid + i * 256;
                int row = f >> 3, q = f & 7;
                st[i] = *(const float4*)(X + (size_t)(node0 + row) * HIDDEN
                                           + (c + 1) * CHUNK + q * 4);
            }
        }

        // 4 k-steps of 8 in this chunk
        #pragma unroll
        for (int ks = 0; ks < 4; ks++) {
            int kt = c * 4 + ks;   // global k-tile 0..15
            uint32_t a[2][4];
            #pragma unroll
            for (int mt = 0; mt < 2; mt++) {
                int r0  = wm * 32 + mt * 16 + g;
                int col = ks * 8 + tg;
                a[mt][0] = __float_as_uint(buf[r0 * XS_STRIDE + col]);
                a[mt][1] = __float_as_uint(buf[(r0 + 8) * XS_STRIDE + col]);
                a[mt][2] = __float_as_uint(buf[r0 * XS_STRIDE + col + 4]);
                a[mt][3] = __float_as_uint(buf[(r0 + 8) * XS_STRIDE + col + 4]);
            }
            #pragma unroll
            for (int nt = 0; nt < 8; nt++) {
                float2 b = sW[(kt * 16 + wn * 8 + nt) * 32 + lane];
                uint32_t b0 = __float_as_uint(b.x);
                uint32_t b1 = __float_as_uint(b.y);
                #pragma unroll
                for (int mt = 0; mt < 2; mt++) {
                    asm volatile(
                        "mma.sync.aligned.m16n8k8.row.col.f32.tf32.tf32.f32 "
                        "{%0,%1,%2,%3}, {%4,%5,%6,%7}, {%8,%9}, {%0,%1,%2,%3};"
                        : "+f"(acc[mt][nt][0]), "+f"(acc[mt][nt][1]),
                          "+f"(acc[mt][nt][2]), "+f"(acc[mt][nt][3])
                        : "r"(a[mt][0]), "r"(a[mt][1]), "r"(a[mt][2]), "r"(a[mt][3]),
                          "r"(b0), "r"(b1));
                }
            }
        }
        __syncthreads();
    }

    // Epilogue: s[m] = sum_n relu(acc + c[n]) * w2[n]; combine across wn halves.
    // acc frag (m16n8): d0=(g, 2tg), d1=(g, 2tg+1), d2=(g+8, 2tg), d3=(g+8, 2tg+1)
    float* part = Xs;  // reuse (safe: synced after last compute)
    #pragma unroll
    for (int mt = 0; mt < 2; mt++) {
        float sA = 0.0f, sB = 0.0f;
        #pragma unroll
        for (int nt = 0; nt < 8; nt++) {
            int n = wn * 64 + nt * 8 + 2 * tg;
            float c0 = g_c[n],     c1 = g_c[n + 1];
            float w0 = W_tp2[n],   w1 = W_tp2[n + 1];
            sA = fmaf(fmaxf(acc[mt][nt][0] + c0, 0.0f), w0, sA);
            sA = fmaf(fmaxf(acc[mt][nt][1] + c1, 0.0f), w1, sA);
            sB = fmaf(fmaxf(acc[mt][nt][2] + c0, 0.0f), w0, sB);
            sB = fmaf(fmaxf(acc[mt][nt][3] + c1, 0.0f), w1, sB);
        }
        sA += __shfl_xor_sync(0xffffffffu, sA, 1);
        sA += __shfl_xor_sync(0xffffffffu, sA, 2);
        sB += __shfl_xor_sync(0xffffffffu, sB, 1);
        sB += __shfl_xor_sync(0xffffffffu, sB, 2);
        if (tg == 0) {
            int rowA = wm * 32 + mt * 16 + g;
            part[rowA * 2 + wn]       = sA;
            part[(rowA + 8) * 2 + wn] = sB;
        }
    }
    __syncthreads();
    if (tid < BM)
        out[HEAD_OFF + node0 + tid] = part[tid * 2] + part[tid * 2 + 1] + b_tp2[0];
}

// ---------------------------------------------------------------------------
extern "C" void kernel_launch(void* const* d_in, const int* in_sizes, int n_in,
                              void* d_out, int out_size)
{
    const float* node_hidden = (const float*)d_in[0];
    const float* h_glob      = (const float*)d_in[1];
    const float* state       = (const float*)d_in[2];
    const float* mask        = (const float*)d_in[3];
    const float* W_hl1 = (const float*)d_in[4];
    const float* b_hl1 = (const float*)d_in[5];
    const float* W_hl2 = (const float*)d_in[6];
    const float* b_hl2 = (const float*)d_in[7];
    const float* W_in1 = (const float*)d_in[8];
    const float* b_in1 = (const float*)d_in[9];
    const float* W_in2 = (const float*)d_in[10];
    const float* b_in2 = (const float*)d_in[11];
    const float* W_ex1 = (const float*)d_in[12];
    const float* b_ex1 = (const float*)d_in[13];
    const float* W_ex2 = (const float*)d_in[14];
    const float* b_ex2 = (const float*)d_in[15];
    const float* W_tp1 = (const float*)d_in[16];
    const float* b_tp1 = (const float*)d_in[17];
    const float* W_tp2 = (const float*)d_in[18];
    const float* b_tp2 = (const float*)d_in[19];
    float* out = (float*)d_out;

    head_kernel<<<1, 128>>>(node_hidden, h_glob, state, mask,
                            W_hl1, b_hl1, W_hl2, b_hl2,
                            W_in1, b_in1, W_in2, b_in2,
                            W_ex1, b_ex1, W_ex2, b_ex2,
                            W_tp1, b_tp1, out);

    const int smem_bytes = 16384 * 4 + 2 * BM * XS_STRIDE * 4;  // 102400
    static bool attr_set = false;
    if (!attr_set) {
        cudaFuncSetAttribute(teleport_kernel,
                             cudaFuncAttributeMaxDynamicSharedMemorySize,
                             smem_bytes);
        attr_set = true;
    }
    teleport_kernel<<<N_NODES / BM, 256, smem_bytes>>>(
        node_hidden, W_tp2, b_tp2, out);
}

// round 6
// speedup vs baseline: 2.7374x; 1.4923x over previous
#include <cuda_runtime.h>
#include <math.h>
#include <stdint.h>

#define HIDDEN   128
#define FEATURE  264
#define N_NODES  400000
#define HEAD_OFF 39     // 4 + 5 + 30 outputs before teleport logits

#define BM        256   // nodes per block
#define CHUNK      32   // K per staging chunk
#define XS_STRIDE  36   // 36 % 32 == 4 -> conflict-free A-fragment LDS; 144B row (16B mult)
#define NCHUNKS     4   // 128 / 32

// c[j] = b_tp1[j] + h_glob @ W_tp1[0:128, j] + state @ W_tp1[256:264, j]
__device__ float  g_c[HIDDEN];
// Prepacked tf32 B fragments of W_tp1[128:256,:]: [kt(16)][nt(16)][lane(32)] -> (b0,b1)
__device__ float2 g_Wfrag[16 * 16 * 32];

__device__ __forceinline__ uint32_t f2tf(float x) {
    uint32_t r;
    asm("cvt.rna.tf32.f32 %0, %1;" : "=r"(r) : "f"(x));
    return r;
}

__device__ __forceinline__ void cp16(uint32_t saddr, const void* gaddr) {
    asm volatile("cp.async.cg.shared.global [%0], [%1], 16;"
                 :: "r"(saddr), "l"(gaddr));
}
__device__ __forceinline__ void cp_commit() {
    asm volatile("cp.async.commit_group;");
}

// ---------------------------------------------------------------------------
// prep_kernel: grid 12 x 256.
//   blocks 0-7 : prepack W fragments (1024 float2 each)
//   block  8   : g_c
//   blocks 9-11: the three head FFNs
// ---------------------------------------------------------------------------
__global__ void __launch_bounds__(256) prep_kernel(
    const float* __restrict__ node_hidden, const float* __restrict__ h_glob,
    const float* __restrict__ state,       const float* __restrict__ mask,
    const float* __restrict__ W_hl1, const float* __restrict__ b_hl1,
    const float* __restrict__ W_hl2, const float* __restrict__ b_hl2,
    const float* __restrict__ W_in1, const float* __restrict__ b_in1,
    const float* __restrict__ W_in2, const float* __restrict__ b_in2,
    const float* __restrict__ W_ex1, const float* __restrict__ b_ex1,
    const float* __restrict__ W_ex2, const float* __restrict__ b_ex2,
    const float* __restrict__ W_tp1, const float* __restrict__ b_tp1,
    float* __restrict__ out)
{
    const int blk = blockIdx.x;
    const int tid = threadIdx.x;

    if (blk < 8) {
        // ---- prepack 1024 float2 per block (4 per thread) ----
        #pragma unroll
        for (int r = 0; r < 4; r++) {
            int idx = blk * 1024 + r * 256 + tid;
            int t  = idx & 31;
            int nt = (idx >> 5) & 15;
            int kt = idx >> 9;
            int k0 = 128 + kt * 8 + (t & 3);
            int n  = nt * 8 + (t >> 2);
            float b0 = W_tp1[(size_t)k0 * HIDDEN + n];
            float b1 = W_tp1[(size_t)(k0 + 4) * HIDDEN + n];
            g_Wfrag[idx] = make_float2(__uint_as_float(f2tf(b0)),
                                       __uint_as_float(f2tf(b1)));
        }
        return;
    }

    if (blk == 8) {
        // ---- g_c: split the 136-dim reduction over 2 halves ----
        __shared__ float part[2][HIDDEN];
        int j = tid & 127, half = tid >> 7;
        float c = 0.0f;
        if (half == 0) {
            #pragma unroll 8
            for (int k = 0; k < 64; k++)
                c = fmaf(h_glob[k], W_tp1[k * HIDDEN + j], c);
        } else {
            #pragma unroll 8
            for (int k = 64; k < 128; k++)
                c = fmaf(h_glob[k], W_tp1[k * HIDDEN + j], c);
            #pragma unroll
            for (int k = 0; k < 8; k++)
                c = fmaf(state[k], W_tp1[(256 + k) * HIDDEN + j], c);
            c += b_tp1[j];
        }
        part[half][j] = c;
        __syncthreads();
        if (tid < HIDDEN) g_c[tid] = part[0][tid] + part[1][tid];
        return;
    }

    // ---- heads: one block per head, k split over 2 halves ----
    __shared__ float feats[FEATURE];
    __shared__ float part[2][HIDDEN];
    __shared__ float hid[HIDDEN];

    const int h = blk - 9;
    const float* W1 = (h == 0) ? W_hl1 : (h == 1) ? W_in1 : W_ex1;
    const float* b1 = (h == 0) ? b_hl1 : (h == 1) ? b_in1 : b_ex1;
    const float* W2 = (h == 0) ? W_hl2 : (h == 1) ? W_in2 : W_ex2;
    const float* b2 = (h == 0) ? b_hl2 : (h == 1) ? b_in2 : b_ex2;
    const int outd  = (h == 0) ? 4 : (h == 1) ? 5 : 30;
    const int ooff  = (h == 0) ? 0 : (h == 1) ? 4 : 9;

    if (tid < 128) {
        feats[tid]       = node_hidden[tid];   // cur = node 0
        feats[128 + tid] = h_glob[tid];
        if (tid < 8) feats[256 + tid] = state[tid];
    }
    __syncthreads();

    const int j = tid & 127, half = tid >> 7;
    const int k0 = half * 132, k1 = k0 + 132;
    float a = 0.0f;
    #pragma unroll 8
    for (int k = k0; k < k1; k++)
        a = fmaf(feats[k], W1[k * HIDDEN + j], a);
    part[half][j] = a;
    __syncthreads();
    if (tid < HIDDEN)
        hid[tid] = fmaxf(part[0][tid] + part[1][tid] + b1[tid], 0.0f);
    __syncthreads();

    if (tid < outd) {
        float o = b2[tid];
        #pragma unroll 8
        for (int k = 0; k < HIDDEN; k++)
            o = fmaf(hid[k], W2[k * outd + tid], o);
        if (h == 2) o += logf(mask[tid]);
        out[ooff + tid] = o;
    }
}

// ---------------------------------------------------------------------------
// teleport_kernel v2: tf32 mma, BM=256, warp tile m64 x n64 (mt=4, nt=8),
// cp.async staging of X (raw fp32 in smem, cvt after LDS).
//   H = relu(c + X @ W), y = H @ w2 + b2. Only y is written.
// ---------------------------------------------------------------------------
__global__ void __launch_bounds__(256, 1) teleport_kernel(
    const float* __restrict__ X, const float* __restrict__ W_tp2,
    const float* __restrict__ b_tp2, float* __restrict__ out)
{
    extern __shared__ float smem[];
    float2* sW = (float2*)smem;            // 16384 floats = 64KB
    float*  Xs = smem + 16384;             // 2 x 256 x 36 floats

    const int tid  = threadIdx.x;
    const int lane = tid & 31;
    const int warp = tid >> 5;
    const int wm   = warp & 3;       // m group (4 x 64 rows)
    const int wn   = warp >> 2;      // n group (2 x 64 cols)
    const int g    = lane >> 2;      // groupID (0..7)
    const int tg   = lane & 3;       // thread-in-group (0..3)
    const int node0 = blockIdx.x * BM;

    const uint32_t sW_b = (uint32_t)__cvta_generic_to_shared(sW);
    const uint32_t Xs_b = (uint32_t)__cvta_generic_to_shared(Xs);

    // Group 0: W fragments (4096 float4) + X chunk 0
    #pragma unroll
    for (int i = 0; i < 16; i++) {
        int f = tid + i * 256;
        cp16(sW_b + f * 16, (const char*)g_Wfrag + f * 16);
    }
    #pragma unroll
    for (int i = 0; i < 8; i++) {
        int f = tid + i * 256;            // 0..2047
        int row = f >> 3, q = f & 7;
        size_t grow = node0 + row; if (grow >= N_NODES) grow = N_NODES - 1;
        cp16(Xs_b + (row * XS_STRIDE + q * 4) * 4,
             X + grow * HIDDEN + q * 4);
    }
    cp_commit();

    float acc[4][8][4];
    #pragma unroll
    for (int mt = 0; mt < 4; mt++)
        #pragma unroll
        for (int nt = 0; nt < 8; nt++)
            #pragma unroll
            for (int r = 0; r < 4; r++) acc[mt][nt][r] = 0.0f;

    #pragma unroll
    for (int c = 0; c < NCHUNKS; c++) {
        if (c < NCHUNKS - 1) {
            uint32_t dstb = Xs_b + ((c + 1) & 1) * (BM * XS_STRIDE * 4);
            #pragma unroll
            for (int i = 0; i < 8; i++) {
                int f = tid + i * 256;
                int row = f >> 3, q = f & 7;
                size_t grow = node0 + row; if (grow >= N_NODES) grow = N_NODES - 1;
                cp16(dstb + (row * XS_STRIDE + q * 4) * 4,
                     X + grow * HIDDEN + (c + 1) * CHUNK + q * 4);
            }
            cp_commit();
            asm volatile("cp.async.wait_group 1;");
        } else {
            asm volatile("cp.async.wait_group 0;");
        }
        __syncthreads();

        float* buf = Xs + (c & 1) * (BM * XS_STRIDE);
        #pragma unroll
        for (int ks = 0; ks < 4; ks++) {
            int kt = c * 4 + ks;
            int col = ks * 8 + tg;
            uint32_t a[4][4];
            #pragma unroll
            for (int mt = 0; mt < 4; mt++) {
                int r0 = wm * 64 + mt * 16 + g;
                a[mt][0] = f2tf(buf[r0 * XS_STRIDE + col]);
                a[mt][1] = f2tf(buf[(r0 + 8) * XS_STRIDE + col]);
                a[mt][2] = f2tf(buf[r0 * XS_STRIDE + col + 4]);
                a[mt][3] = f2tf(buf[(r0 + 8) * XS_STRIDE + col + 4]);
            }
            #pragma unroll
            for (int nt = 0; nt < 8; nt++) {
                float2 b = sW[(kt * 16 + wn * 8 + nt) * 32 + lane];
                uint32_t b0 = __float_as_uint(b.x);
                uint32_t b1 = __float_as_uint(b.y);
                #pragma unroll
                for (int mt = 0; mt < 4; mt++) {
                    asm volatile(
                        "mma.sync.aligned.m16n8k8.row.col.f32.tf32.tf32.f32 "
                        "{%0,%1,%2,%3}, {%4,%5,%6,%7}, {%8,%9}, {%0,%1,%2,%3};"
                        : "+f"(acc[mt][nt][0]), "+f"(acc[mt][nt][1]),
                          "+f"(acc[mt][nt][2]), "+f"(acc[mt][nt][3])
                        : "r"(a[mt][0]), "r"(a[mt][1]), "r"(a[mt][2]), "r"(a[mt][3]),
                          "r"(b0), "r"(b1));
                }
            }
        }
        __syncthreads();
    }

    // Epilogue: s[m] = sum_n relu(acc + c[n]) * w2[n]; combine across wn halves.
    // acc frag (m16n8): d0=(g, 2tg), d1=(g, 2tg+1), d2=(g+8, 2tg), d3=(g+8, 2tg+1)
    float* part = Xs;  // reuse (synced after last compute)
    #pragma unroll
    for (int mt = 0; mt < 4; mt++) {
        float sA = 0.0f, sB = 0.0f;
        #pragma unroll
        for (int nt = 0; nt < 8; nt++) {
            int n = wn * 64 + nt * 8 + 2 * tg;
            float c0 = g_c[n],     c1 = g_c[n + 1];
            float w0 = W_tp2[n],   w1 = W_tp2[n + 1];
            sA = fmaf(fmaxf(acc[mt][nt][0] + c0, 0.0f), w0, sA);
            sA = fmaf(fmaxf(acc[mt][nt][1] + c1, 0.0f), w1, sA);
            sB = fmaf(fmaxf(acc[mt][nt][2] + c0, 0.0f), w0, sB);
            sB = fmaf(fmaxf(acc[mt][nt][3] + c1, 0.0f), w1, sB);
        }
        sA += __shfl_xor_sync(0xffffffffu, sA, 1);
        sA += __shfl_xor_sync(0xffffffffu, sA, 2);
        sB += __shfl_xor_sync(0xffffffffu, sB, 1);
        sB += __shfl_xor_sync(0xffffffffu, sB, 2);
        if (tg == 0) {
            int rowA = wm * 64 + mt * 16 + g;
            part[rowA * 2 + wn]       = sA;
            part[(rowA + 8) * 2 + wn] = sB;
        }
    }
    __syncthreads();
    {
        int nd = node0 + tid;
        if (nd < N_NODES)
            out[HEAD_OFF + nd] = part[tid * 2] + part[tid * 2 + 1] + b_tp2[0];
    }
}

// ---------------------------------------------------------------------------
extern "C" void kernel_launch(void* const* d_in, const int* in_sizes, int n_in,
                              void* d_out, int out_size)
{
    const float* node_hidden = (const float*)d_in[0];
    const float* h_glob      = (const float*)d_in[1];
    const float* state       = (const float*)d_in[2];
    const float* mask        = (const float*)d_in[3];
    const float* W_hl1 = (const float*)d_in[4];
    const float* b_hl1 = (const float*)d_in[5];
    const float* W_hl2 = (const float*)d_in[6];
    const float* b_hl2 = (const float*)d_in[7];
    const float* W_in1 = (const float*)d_in[8];
    const float* b_in1 = (const float*)d_in[9];
    const float* W_in2 = (const float*)d_in[10];
    const float* b_in2 = (const float*)d_in[11];
    const float* W_ex1 = (const float*)d_in[12];
    const float* b_ex1 = (const float*)d_in[13];
    const float* W_ex2 = (const float*)d_in[14];
    const float* b_ex2 = (const float*)d_in[15];
    const float* W_tp1 = (const float*)d_in[16];
    const float* b_tp1 = (const float*)d_in[17];
    const float* W_tp2 = (const float*)d_in[18];
    const float* b_tp2 = (const float*)d_in[19];
    float* out = (float*)d_out;

    prep_kernel<<<12, 256>>>(node_hidden, h_glob, state, mask,
                             W_hl1, b_hl1, W_hl2, b_hl2,
                             W_in1, b_in1, W_in2, b_in2,
                             W_ex1, b_ex1, W_ex2, b_ex2,
                             W_tp1, b_tp1, out);

    const int smem_bytes = (16384 + 2 * BM * XS_STRIDE) * 4;  // 139264
    static bool attr_set = false;
    if (!attr_set) {
        cudaFuncSetAttribute(teleport_kernel,
                             cudaFuncAttributeMaxDynamicSharedMemorySize,
                             smem_bytes);
        attr_set = true;
    }
    teleport_kernel<<<(N_NODES + BM - 1) / BM, 256, smem_bytes>>>(
        node_hidden, W_tp2, b_tp2, out);
}

// round 10
// speedup vs baseline: 3.3902x; 1.2385x over previous
#include <cuda_runtime.h>
#include <math.h>
#include <stdint.h>

#define HIDDEN   128
#define FEATURE  264
#define N_NODES  400000
#define HEAD_OFF 39     // 4 + 5 + 30 outputs before teleport logits

#define BM        256   // nodes per block
#define CHUNK      32   // K per staging chunk
#define WS_STRIDE 136   // 136 % 32 == 8 -> conflict-free B-fragment LDS
#define XS_STRIDE  36   // 36 % 32 == 4 -> conflict-free A-fragment LDS
#define NCHUNKS     4   // 128 / 32

__device__ __forceinline__ uint32_t f2tf(float x) {
    uint32_t r;
    asm("cvt.rna.tf32.f32 %0, %1;" : "=r"(r) : "f"(x));
    return r;
}

__device__ __forceinline__ void cp16(uint32_t saddr, const void* gaddr) {
    asm volatile("cp.async.cg.shared.global [%0], [%1], 16;"
                 :: "r"(saddr), "l"(gaddr));
}
__device__ __forceinline__ void cp_commit() {
    asm volatile("cp.async.commit_group;");
}

// ---------------------------------------------------------------------------
// Single fused kernel.
//  All blocks: tf32 mma teleport GEMM for 256 nodes
//    H = relu(c + X @ W), y = H @ w2 + b2 (c computed per-block, W loaded raw)
//  Blocks 0-2: additionally run one head FFN each after the epilogue.
// ---------------------------------------------------------------------------
__global__ void __launch_bounds__(256, 1) fused_kernel(
    const float* __restrict__ X,      const float* __restrict__ h_glob,
    const float* __restrict__ state,  const float* __restrict__ mask,
    const float* __restrict__ W_hl1, const float* __restrict__ b_hl1,
    const float* __restrict__ W_hl2, const float* __restrict__ b_hl2,
    const float* __restrict__ W_in1, const float* __restrict__ b_in1,
    const float* __restrict__ W_in2, const float* __restrict__ b_in2,
    const float* __restrict__ W_ex1, const float* __restrict__ b_ex1,
    const float* __restrict__ W_ex2, const float* __restrict__ b_ex2,
    const float* __restrict__ W_tp1, const float* __restrict__ b_tp1,
    const float* __restrict__ W_tp2, const float* __restrict__ b_tp2,
    float* __restrict__ out)
{
    extern __shared__ float smem[];
    float* Ws = smem;                  // 128 x 136 = 17408 floats (raw fp32 W)
    float* Xs = smem + 17408;          // 2 x 256 x 36 = 18432 floats

    __shared__ float c_s[HIDDEN];
    __shared__ float cpart[2][HIDDEN];

    const int tid  = threadIdx.x;
    const int lane = tid & 31;
    const int warp = tid >> 5;
    const int wm   = warp & 3;       // m group (4 x 64 rows)
    const int wn   = warp >> 2;      // n group (2 x 64 cols)
    const int g    = lane >> 2;      // groupID (0..7)
    const int tg   = lane & 3;       // thread-in-group (0..3)
    const int node0 = blockIdx.x * BM;

    const uint32_t Ws_b = (uint32_t)__cvta_generic_to_shared(Ws);
    const uint32_t Xs_b = (uint32_t)__cvta_generic_to_shared(Xs);

    // Group 0: raw W (rows 128..255 of W_tp1; 4096 float4) + X chunk 0
    #pragma unroll
    for (int i = 0; i < 16; i++) {
        int f = tid + i * 256;            // 0..4095
        int row = f >> 5, q = f & 31;     // 32 float4 per 128-float row
        cp16(Ws_b + (row * WS_STRIDE + q * 4) * 4,
             W_tp1 + (size_t)(128 + row) * HIDDEN + q * 4);
    }
    #pragma unroll
    for (int i = 0; i < 8; i++) {
        int f = tid + i * 256;            // 0..2047
        int row = f >> 3, q = f & 7;
        size_t grow = node0 + row; if (grow >= N_NODES) grow = N_NODES - 1;
        cp16(Xs_b + (row * XS_STRIDE + q * 4) * 4,
             X + grow * HIDDEN + q * 4);
    }
    cp_commit();

    // c[j] partials (overlaps cp.async latency). W_tp1 rows 0..127 are
    // L2-broadcast across all blocks.
    {
        int j = tid & 127, half = tid >> 7;
        float cv = 0.0f;
        int kb = half * 64;
        #pragma unroll 8
        for (int k = kb; k < kb + 64; k++)
            cv = fmaf(h_glob[k], W_tp1[k * HIDDEN + j], cv);
        if (half) {
            #pragma unroll
            for (int k = 0; k < 8; k++)
                cv = fmaf(state[k], W_tp1[(256 + k) * HIDDEN + j], cv);
            cv += b_tp1[j];
        }
        cpart[half][j] = cv;
    }

    float acc[4][8][4];
    #pragma unroll
    for (int mt = 0; mt < 4; mt++)
        #pragma unroll
        for (int nt = 0; nt < 8; nt++)
            #pragma unroll
            for (int r = 0; r < 4; r++) acc[mt][nt][r] = 0.0f;

    #pragma unroll
    for (int c = 0; c < NCHUNKS; c++) {
        if (c < NCHUNKS - 1) {
            uint32_t dstb = Xs_b + ((c + 1) & 1) * (BM * XS_STRIDE * 4);
            #pragma unroll
            for (int i = 0; i < 8; i++) {
                int f = tid + i * 256;
                int row = f >> 3, q = f & 7;
                size_t grow = node0 + row; if (grow >= N_NODES) grow = N_NODES - 1;
                cp16(dstb + (row * XS_STRIDE + q * 4) * 4,
                     X + grow * HIDDEN + (c + 1) * CHUNK + q * 4);
            }
            cp_commit();
            asm volatile("cp.async.wait_group 1;");
        } else {
            asm volatile("cp.async.wait_group 0;");
        }
        __syncthreads();

        if (c == 0 && tid < HIDDEN)
            c_s[tid] = cpart[0][tid] + cpart[1][tid];

        float* buf = Xs + (c & 1) * (BM * XS_STRIDE);
        #pragma unroll
        for (int ks = 0; ks < 4; ks++) {
            int kt = c * 4 + ks;
            int col = ks * 8 + tg;
            uint32_t a[4][4];
            #pragma unroll
            for (int mt = 0; mt < 4; mt++) {
                int r0 = wm * 64 + mt * 16 + g;
                a[mt][0] = f2tf(buf[r0 * XS_STRIDE + col]);
                a[mt][1] = f2tf(buf[(r0 + 8) * XS_STRIDE + col]);
                a[mt][2] = f2tf(buf[r0 * XS_STRIDE + col + 4]);
                a[mt][3] = f2tf(buf[(r0 + 8) * XS_STRIDE + col + 4]);
            }
            // B fragments from raw-layout Ws: row = kt*8 + tg (+4), col = n + g
            const float* wrow = Ws + (kt * 8 + tg) * WS_STRIDE + wn * 64 + g;
            #pragma unroll
            for (int nt = 0; nt < 8; nt++) {
                uint32_t b0 = f2tf(wrow[nt * 8]);
                uint32_t b1 = f2tf(wrow[4 * WS_STRIDE + nt * 8]);
                #pragma unroll
                for (int mt = 0; mt < 4; mt++) {
                    asm volatile(
                        "mma.sync.aligned.m16n8k8.row.col.f32.tf32.tf32.f32 "
                        "{%0,%1,%2,%3}, {%4,%5,%6,%7}, {%8,%9}, {%0,%1,%2,%3};"
                        : "+f"(acc[mt][nt][0]), "+f"(acc[mt][nt][1]),
                          "+f"(acc[mt][nt][2]), "+f"(acc[mt][nt][3])
                        : "r"(a[mt][0]), "r"(a[mt][1]), "r"(a[mt][2]), "r"(a[mt][3]),
                          "r"(b0), "r"(b1));
                }
            }
        }
        __syncthreads();
    }

    // Epilogue: s[m] = sum_n relu(acc + c[n]) * w2[n]; combine across wn halves.
    // acc frag (m16n8): d0=(g, 2tg), d1=(g, 2tg+1), d2=(g+8, 2tg), d3=(g+8, 2tg+1)
    float* part = Xs;  // reuse (synced after last compute)
    #pragma unroll
    for (int mt = 0; mt < 4; mt++) {
        float sA = 0.0f, sB = 0.0f;
        #pragma unroll
        for (int nt = 0; nt < 8; nt++) {
            int n = wn * 64 + nt * 8 + 2 * tg;
            float c0 = c_s[n],     c1 = c_s[n + 1];
            float w0 = W_tp2[n],   w1 = W_tp2[n + 1];
            sA = fmaf(fmaxf(acc[mt][nt][0] + c0, 0.0f), w0, sA);
            sA = fmaf(fmaxf(acc[mt][nt][1] + c1, 0.0f), w1, sA);
            sB = fmaf(fmaxf(acc[mt][nt][2] + c0, 0.0f), w0, sB);
            sB = fmaf(fmaxf(acc[mt][nt][3] + c1, 0.0f), w1, sB);
        }
        sA += __shfl_xor_sync(0xffffffffu, sA, 1);
        sA += __shfl_xor_sync(0xffffffffu, sA, 2);
        sB += __shfl_xor_sync(0xffffffffu, sB, 1);
        sB += __shfl_xor_sync(0xffffffffu, sB, 2);
        if (tg == 0) {
            int rowA = wm * 64 + mt * 16 + g;
            part[rowA * 2 + wn]       = sA;
            part[(rowA + 8) * 2 + wn] = sB;
        }
    }
    __syncthreads();
    {
        int nd = node0 + tid;
        if (nd < N_NODES)
            out[HEAD_OFF + nd] = part[tid * 2] + part[tid * 2 + 1] + b_tp2[0];
    }

    // ---- Blocks 0-2: head FFNs on feats = [node_hidden[0] | h_glob | state]
    if (blockIdx.x < 3) {
        float* feats = Xs + 1024;        // 264  (past 'part' region)
        float* hpart = feats + 264;      // 256
        float* hid   = hpart + 256;      // 128

        const int h = blockIdx.x;
        const float* W1 = (h == 0) ? W_hl1 : (h == 1) ? W_in1 : W_ex1;
        const float* b1 = (h == 0) ? b_hl1 : (h == 1) ? b_in1 : b_ex1;
        const float* W2 = (h == 0) ? W_hl2 : (h == 1) ? W_in2 : W_ex2;
        const float* b2 = (h == 0) ? b_hl2 : (h == 1) ? b_in2 : b_ex2;
        const int outd  = (h == 0) ? 4 : (h == 1) ? 5 : 30;
        const int ooff  = (h == 0) ? 0 : (h == 1) ? 4 : 9;

        if (tid < 128) {
            feats[tid]       = X[tid];        // cur = node 0
            feats[128 + tid] = h_glob[tid];
            if (tid < 8) feats[256 + tid] = state[tid];
        }
        __syncthreads();

        const int j = tid & 127, half = tid >> 7;
        const int k0 = half * 132, k1 = k0 + 132;
        float a = 0.0f;
        #pragma unroll 8
        for (int k = k0; k < k1; k++)
            a = fmaf(feats[k], W1[k * HIDDEN + j], a);
        hpart[half * 128 + j] = a;
        __syncthreads();
        if (tid < HIDDEN)
            hid[tid] = fmaxf(hpart[tid] + hpart[128 + tid] + b1[tid], 0.0f);
        __syncthreads();

        if (tid < outd) {
            float o = b2[tid];
            #pragma unroll 8
            for (int k = 0; k < HIDDEN; k++)
                o = fmaf(hid[k], W2[k * outd + tid], o);
            if (h == 2) o += logf(mask[tid]);
            out[ooff + tid] = o;
        }
    }
}

// ---------------------------------------------------------------------------
extern "C" void kernel_launch(void* const* d_in, const int* in_sizes, int n_in,
                              void* d_out, int out_size)
{
    const float* node_hidden = (const float*)d_in[0];
    const float* h_glob      = (const float*)d_in[1];
    const float* state       = (const float*)d_in[2];
    const float* mask        = (const float*)d_in[3];
    const float* W_hl1 = (const float*)d_in[4];
    const float* b_hl1 = (const float*)d_in[5];
    const float* W_hl2 = (const float*)d_in[6];
    const float* b_hl2 = (const float*)d_in[7];
    const float* W_in1 = (const float*)d_in[8];
    const float* b_in1 = (const float*)d_in[9];
    const float* W_in2 = (const float*)d_in[10];
    const float* b_in2 = (const float*)d_in[11];
    const float* W_ex1 = (const float*)d_in[12];
    const float* b_ex1 = (const float*)d_in[13];
    const float* W_ex2 = (const float*)d_in[14];
    const float* b_ex2 = (const float*)d_in[15];
    const float* W_tp1 = (const float*)d_in[16];
    const float* b_tp1 = (const float*)d_in[17];
    const float* W_tp2 = (const float*)d_in[18];
    const float* b_tp2 = (const float*)d_in[19];
    float* out = (float*)d_out;

    const int smem_bytes = (17408 + 18432) * 4;  // 143360
    static bool attr_set = false;
    if (!attr_set) {
        cudaFuncSetAttribute(fused_kernel,
                             cudaFuncAttributeMaxDynamicSharedMemorySize,
                             smem_bytes);
        attr_set = true;
    }
    fused_kernel<<<(N_NODES + BM - 1) / BM, 256, smem_bytes>>>(
        node_hidden, h_glob, state, mask,
        W_hl1, b_hl1, W_hl2, b_hl2,
        W_in1, b_in1, W_in2, b_in2,
        W_ex1, b_ex1, W_ex2, b_ex2,
        W_tp1, b_tp1, W_tp2, b_tp2, out);
}